// round 16
// baseline (speedup 1.0000x reference)
#include <cuda_runtime.h>
#include <cuda_fp16.h>
#include <cstdint>
#include <math.h>

#define E_TOT 102400
#define N_TOT 100000
#define NGRAPH 64
#define D_IN   1408
#define H1     512
#define H2     512
#define H3     256

// ---------------- scratch (__device__ globals; no allocs allowed) ----------
// All fp16 activation buffers are stored k2-PERMUTED: within each group of
// 8 u32 (16 halfs), u32 l sits at position (l<4 ? 2l : 2l-7), so the MMA
// fragment pair (k2, k2+4) is adjacent -> one LDS.64.
__device__ __half   g_hfeat[(size_t)E_TOT * 256];
__device__ __half   g_hnodes[(size_t)N_TOT * 256];
__device__ __half   g_hgfeat[(size_t)NGRAPH * 128];
// W pair-packed: pair-row pr=(g*4+l) holds, at u32 col 2n/2n+1, half2 for
// k2=g*8+l and k2+4. Rows: KDIM/4, width 2*N u32.
__device__ uint32_t g_W1p[(size_t)(D_IN / 4) * 2 * H1];
__device__ uint32_t g_W2p[(size_t)(H1 / 4) * 2 * H2];
__device__ uint32_t g_W3p[(size_t)(H2 / 4) * 2 * H3];
__device__ __half   g_hY1[(size_t)E_TOT * H1];   // k2-permuted
__device__ __half   g_hY2[(size_t)E_TOT * H2];   // k2-permuted
__device__ float    g_Hf[(size_t)E_TOT * H3];    // sigmoid out (fp32) for LN
__device__ int      g_gcum[NGRAPH + 1];

// ---------------- helpers ---------------------------------------------------
#define CP_ASYNC16(dst, src) \
    asm volatile("cp.async.cg.shared.global [%0], [%1], 16;" :: "r"(dst), "l"(src) : "memory")
#define CP_COMMIT() asm volatile("cp.async.commit_group;" ::: "memory")
#define CP_WAIT(n)  asm volatile("cp.async.wait_group %0;" :: "n"(n) : "memory")

__device__ __forceinline__ uint32_t smem_u32(const void* p) {
    uint32_t a;
    asm("{ .reg .u64 t; cvta.to.shared.u64 t, %1; cvt.u32.u64 %0, t; }"
        : "=r"(a) : "l"(p));
    return a;
}

// m16n8k16 fp16 mma, fp32 accumulate
__device__ __forceinline__ void mma_f16(float* c, uint32_t a0, uint32_t a1,
                                        uint32_t a2, uint32_t a3,
                                        uint32_t b0, uint32_t b1) {
    asm volatile(
        "mma.sync.aligned.m16n8k16.row.col.f32.f16.f16.f32 "
        "{%0,%1,%2,%3}, {%4,%5,%6,%7}, {%8,%9}, {%0,%1,%2,%3};"
        : "+f"(c[0]), "+f"(c[1]), "+f"(c[2]), "+f"(c[3])
        : "r"(a0), "r"(a1), "r"(a2), "r"(a3), "r"(b0), "r"(b1));
}

// permute u32 index within its 8-group: l<4 -> 2l ; l>=4 -> 2l-7
__host__ __device__ __forceinline__ int uperm(int u) {
    int l = u & 7;
    return (u & ~7) | ((l < 4) ? (2 * l) : (2 * l - 7));
}

// ---------------- pre-pass kernels ------------------------------------------
__global__ void k_prefix(const int* __restrict__ num) {
    if (threadIdx.x == 0) {
        int s = 0;
        g_gcum[0] = 0;
        for (int i = 0; i < NGRAPH; i++) { s += num[i]; g_gcum[i + 1] = s; }
    }
}

// fp32 -> fp16, k2-permuted store (two scalar u32 stores per float4)
__global__ void __launch_bounds__(256) k_cvt(
    const float4* __restrict__ src, uint32_t* __restrict__ dst, int n4)
{
    int i = blockIdx.x * 256 + threadIdx.x;
    if (i < n4) {
        float4 v = src[i];
        __half2 lo = __floats2half2_rn(v.x, v.y);
        __half2 hi = __floats2half2_rn(v.z, v.w);
        dst[uperm(2 * i)]     = *(uint32_t*)&lo;
        dst[uperm(2 * i + 1)] = *(uint32_t*)&hi;
    }
}

// W[k][n] fp32 -> pair-packed Wpp[pr][2n|2n+1]
__global__ void __launch_bounds__(256) k_packW(
    const float* __restrict__ W, uint32_t* __restrict__ Wpp, int K2, int N)
{
    int i = blockIdx.x * 256 + threadIdx.x;   // over (K2/2) * N pair-entries
    if (i < (K2 / 2) * N) {
        int pr = i / N, n = i - pr * N;
        int g = pr >> 2, l = pr & 3;
        int k2a = g * 8 + l;                  // pairs with k2a+4
        __half2 va = __floats2half2_rn(W[(size_t)(2 * k2a) * N + n],
                                       W[(size_t)(2 * k2a + 1) * N + n]);
        __half2 vb = __floats2half2_rn(W[(size_t)(2 * (k2a + 4)) * N + n],
                                       W[(size_t)(2 * (k2a + 4) + 1) * N + n]);
        Wpp[(size_t)pr * 2 * N + 2 * n]     = *(uint32_t*)&va;
        Wpp[(size_t)pr * 2 * N + 2 * n + 1] = *(uint32_t*)&vb;
    }
}

// ---------------- fp16 tensor-core GEMM (paired LDS.64 fragments) -----------
// BM=128, BN=128, BK=32 (16 k2 = 8 pair-rows of B). 8 warps (4M x 2N), 32x64.
// A smem: 128 rows x 24 u32 (16 permuted data + pad): banks 24g+2t distinct.
// B smem: 8 pair-rows x 264 u32 (256 data + pad): banks 8t+2g(+16) distinct.
// 3 cp.async stages, one __syncthreads per chunk, frag double-buffer.
// MODE 0: A gathered (permuted fp16); MODE 1: A dense permuted fp16.
// EPI 0: relu -> fp16 Yh PERMUTED; EPI 1: sigmoid -> fp32 Yf linear.
template<int KDIM, int MODE, int EPI, int HOUT>
__global__ void __launch_bounds__(256, 2) gemm_hmma(
    const __half* __restrict__ Af, const __half* __restrict__ nodes,
    const __half* __restrict__ gfeat, const int* __restrict__ ind,
    const uint32_t* __restrict__ Wpp, const float* __restrict__ bias,
    __half* __restrict__ Yh, float* __restrict__ Yf)
{
    constexpr int PAH = 24, PBN = 264;
    constexpr int STAGEU = 128 * PAH + 8 * PBN;      // 5184 u32 / stage
    constexpr int NC = KDIM / 32;

    extern __shared__ uint32_t smU[];

    const int tid  = threadIdx.x;
    const int wid  = tid >> 5;
    const int lane = tid & 31;
    const int warpM = wid & 3;
    const int warpN = wid >> 2;
    const int eBase = blockIdx.x * 128;
    const int nBase = blockIdx.y * 128;

    const int grp = lane >> 2;       // 0..7
    const int tig = lane & 3;        // 0..3

    float acc[2][8][4];
    #pragma unroll
    for (int i = 0; i < 2; i++)
        #pragma unroll
        for (int j = 0; j < 8; j++)
            #pragma unroll
            for (int u = 0; u < 4; u++) acc[i][j][u] = 0.f;

    // ---- chunk loader ------------------------------------------------------
    const int arow  = tid >> 1;
    const int apart = tid & 1;

    auto load_chunk = [&](int c) {
        uint32_t* As = smU + (c % 3) * STAGEU;
        uint32_t* Bs = As + 128 * PAH;
        const int k0 = c * 32;
        // ---- A (32 halfs = 16 u32 per row; permutation is inside 8-groups,
        //         so contiguous 16-u32 copies preserve it)
        const __half* asrc;
        if (MODE == 0) {
            const int e = eBase + arow;
            if (k0 < 256) {
                asrc = Af + (size_t)e * 256 + k0;
            } else if (k0 < 1280) {
                const int j   = (k0 - 256) >> 8;
                const int nid = __ldg(ind + e * 4 + j);
                asrc = nodes + (size_t)nid * 256 + ((k0 - 256) & 255);
            } else {
                int lo = 0, hi = NGRAPH;
                while (hi - lo > 1) {
                    int mid = (lo + hi) >> 1;
                    if (g_gcum[mid] <= e) lo = mid; else hi = mid;
                }
                asrc = gfeat + (size_t)lo * 128 + (k0 - 1280);
            }
        } else {
            asrc = Af + (size_t)(eBase + arow) * KDIM + k0;
        }
        asrc += apart * 16;
        uint32_t adst = smem_u32(As + arow * PAH + apart * 8);
        CP_ASYNC16(adst,      asrc);
        CP_ASYNC16(adst + 16, asrc + 8);
        // ---- B: pair-rows c*8 .. c*8+7, u32 cols [2*nBase, 2*nBase+256)
        #pragma unroll
        for (int i = 0; i < 2; i++) {
            const int c16 = tid * 2 + i;          // 0..511 16B chunks
            const int row = c16 >> 6;             // 0..7
            const int col = (c16 & 63) * 4;       // u32 col in tile
            const uint32_t* bsrc =
                Wpp + (size_t)(c * 8 + row) * (2 * HOUT) + 2 * nBase + col;
            CP_ASYNC16(smem_u32(Bs + row * PBN + col), bsrc);
        }
        CP_COMMIT();
    };

    // ---- prologue ----------------------------------------------------------
    load_chunk(0);
    if (NC > 1) load_chunk(1);

    for (int c = 0; c < NC; c++) {
        if (c + 1 < NC) CP_WAIT(1); else CP_WAIT(0);
        __syncthreads();
        if (c + 2 < NC) load_chunk(c + 2);

        const uint32_t* As = smU + (c % 3) * STAGEU;
        const uint32_t* Bs = As + 128 * PAH;

        uint2 ap[2][2];     // [ks][mi] : {a0,a2} row m
        uint2 aq[2][2];     // [ks][mi] : {a1,a3} row m+8
        uint2 bp[2][8];     // [ks][ni] : {b0,b1}
        #pragma unroll
        for (int ks = 0; ks < 2; ks++) {
            const int abase = ks * 8 + 2 * tig;
            #pragma unroll
            for (int mi = 0; mi < 2; mi++) {
                const int m = warpM * 32 + mi * 16 + grp;
                ap[ks][mi] = *(const uint2*)(As + m * PAH + abase);
                aq[ks][mi] = *(const uint2*)(As + (m + 8) * PAH + abase);
            }
            const int brow = ks * 4 + tig;
            #pragma unroll
            for (int ni = 0; ni < 8; ni++) {
                const int ncol = 2 * (warpN * 64 + ni * 8 + grp);
                bp[ks][ni] = *(const uint2*)(Bs + brow * PBN + ncol);
            }
        }
        #pragma unroll
        for (int ks = 0; ks < 2; ks++)
            #pragma unroll
            for (int ni = 0; ni < 8; ni++) {
                mma_f16(acc[0][ni], ap[ks][0].x, aq[ks][0].x,
                        ap[ks][0].y, aq[ks][0].y, bp[ks][ni].x, bp[ks][ni].y);
                mma_f16(acc[1][ni], ap[ks][1].x, aq[ks][1].x,
                        ap[ks][1].y, aq[ks][1].y, bp[ks][ni].x, bp[ks][ni].y);
            }
    }

    // ---- epilogue ----------------------------------------------------------
    #pragma unroll
    for (int ni = 0; ni < 8; ni++) {
        const int col = nBase + warpN * 64 + ni * 8 + tig * 2;   // actual n
        const float2 bb = *(const float2*)(bias + col);
        // permuted u32 column for fp16 output (next layer's A layout)
        const int pcol = (nBase >> 1) + warpN * 32 + (ni >> 1) * 8
                       + 2 * tig + (ni & 1);
        #pragma unroll
        for (int mi = 0; mi < 2; mi++) {
            const int e0 = eBase + warpM * 32 + mi * 16 + grp;
            #pragma unroll
            for (int h = 0; h < 2; h++) {
                float x0 = acc[mi][ni][h * 2 + 0] + bb.x;
                float x1 = acc[mi][ni][h * 2 + 1] + bb.y;
                const int er = e0 + h * 8;
                if (EPI == 0) {
                    __half2 v = __floats2half2_rn(fmaxf(x0, 0.f), fmaxf(x1, 0.f));
                    ((uint32_t*)Yh)[(size_t)er * (HOUT / 2) + pcol] = *(uint32_t*)&v;
                } else {
                    float2 v;
                    v.x = 1.f / (1.f + __expf(-x0));
                    v.y = 1.f / (1.f + __expf(-x1));
                    *(float2*)(Yf + (size_t)er * HOUT + col) = v;
                }
            }
        }
    }
}

// ---------------- LayerNorm over last dim (256) ------------------------------
__global__ void __launch_bounds__(256) k_ln(
    const float* __restrict__ H, const float* __restrict__ gamma,
    const float* __restrict__ beta, float* __restrict__ out)
{
    const int row  = blockIdx.x * 8 + (threadIdx.x >> 5);
    const int lane = threadIdx.x & 31;
    const float* hp = H + (size_t)row * 256 + lane * 8;
    float4 v0 = *(const float4*)(hp);
    float4 v1 = *(const float4*)(hp + 4);
    float s  = v0.x + v0.y + v0.z + v0.w + v1.x + v1.y + v1.z + v1.w;
    float sq = v0.x*v0.x + v0.y*v0.y + v0.z*v0.z + v0.w*v0.w
             + v1.x*v1.x + v1.y*v1.y + v1.z*v1.z + v1.w*v1.w;
    #pragma unroll
    for (int o = 16; o > 0; o >>= 1) {
        s  += __shfl_xor_sync(0xFFFFFFFFu, s,  o);
        sq += __shfl_xor_sync(0xFFFFFFFFu, sq, o);
    }
    const float mu  = s * (1.f / 256.f);
    const float var = sq * (1.f / 256.f) - mu * mu;
    const float rs  = rsqrtf(var + 1e-3f);
    const float4 g0 = *(const float4*)(gamma + lane * 8);
    const float4 g1 = *(const float4*)(gamma + lane * 8 + 4);
    const float4 b0 = *(const float4*)(beta + lane * 8);
    const float4 b1 = *(const float4*)(beta + lane * 8 + 4);
    float4 o0, o1;
    o0.x = g0.x * (v0.x - mu) * rs + b0.x;
    o0.y = g0.y * (v0.y - mu) * rs + b0.y;
    o0.z = g0.z * (v0.z - mu) * rs + b0.z;
    o0.w = g0.w * (v0.w - mu) * rs + b0.w;
    o1.x = g1.x * (v1.x - mu) * rs + b1.x;
    o1.y = g1.y * (v1.y - mu) * rs + b1.y;
    o1.z = g1.z * (v1.z - mu) * rs + b1.z;
    o1.w = g1.w * (v1.w - mu) * rs + b1.w;
    float* op = out + (size_t)row * 256 + lane * 8;
    *(float4*)(op)     = o0;
    *(float4*)(op + 4) = o1;
}

// ---------------------------------------------------------------------------
extern "C" void kernel_launch(void* const* d_in, const int* in_sizes, int n_in,
                              void* d_out, int out_size)
{
    const float* feat  = (const float*)d_in[0];
    const float* nodes = (const float*)d_in[1];
    const float* gfeat = (const float*)d_in[2];
    const int*   ind   = (const int*)  d_in[3];
    const int*   num   = (const int*)  d_in[4];
    const float* W1    = (const float*)d_in[5];
    const float* b1    = (const float*)d_in[6];
    const float* W2    = (const float*)d_in[7];
    const float* b2    = (const float*)d_in[8];
    const float* W3    = (const float*)d_in[9];
    const float* b3    = (const float*)d_in[10];
    const float* gamma = (const float*)d_in[11];
    const float* beta  = (const float*)d_in[12];
    float* out = (float*)d_out;

    const int SMEM_BYTES = 3 * (128 * 24 + 8 * 264) * 4;   // 62208

    cudaFuncSetAttribute(gemm_hmma<D_IN, 0, 0, H1>,
                         cudaFuncAttributeMaxDynamicSharedMemorySize, SMEM_BYTES);
    cudaFuncSetAttribute(gemm_hmma<H1, 1, 0, H2>,
                         cudaFuncAttributeMaxDynamicSharedMemorySize, SMEM_BYTES);
    cudaFuncSetAttribute(gemm_hmma<H2, 1, 1, H3>,
                         cudaFuncAttributeMaxDynamicSharedMemorySize, SMEM_BYTES);

    __half *hfeat, *hnodes, *hgfeat, *hY1, *hY2;
    uint32_t *W1p, *W2p, *W3p;
    float *Hf;
    cudaGetSymbolAddress((void**)&hfeat,  g_hfeat);
    cudaGetSymbolAddress((void**)&hnodes, g_hnodes);
    cudaGetSymbolAddress((void**)&hgfeat, g_hgfeat);
    cudaGetSymbolAddress((void**)&W1p,    g_W1p);
    cudaGetSymbolAddress((void**)&W2p,    g_W2p);
    cudaGetSymbolAddress((void**)&W3p,    g_W3p);
    cudaGetSymbolAddress((void**)&hY1,    g_hY1);
    cudaGetSymbolAddress((void**)&hY2,    g_hY2);
    cudaGetSymbolAddress((void**)&Hf,     g_Hf);

    k_prefix<<<1, 32>>>(num);

    // fp32 -> fp16 conversions (k2-permuted)
    {
        int n4 = E_TOT * 256 / 4;
        k_cvt<<<(n4 + 255) / 256, 256>>>((const float4*)feat, (uint32_t*)hfeat, n4);
        n4 = N_TOT * 256 / 4;
        k_cvt<<<(n4 + 255) / 256, 256>>>((const float4*)nodes, (uint32_t*)hnodes, n4);
        n4 = NGRAPH * 128 / 4;
        k_cvt<<<(n4 + 255) / 256, 256>>>((const float4*)gfeat, (uint32_t*)hgfeat, n4);
    }
    // weight pair-packing
    k_packW<<<((D_IN / 4) * H1 + 255) / 256, 256>>>(W1, W1p, D_IN / 2, H1);
    k_packW<<<((H1 / 4) * H2 + 255) / 256, 256>>>(W2, W2p, H1 / 2, H2);
    k_packW<<<((H2 / 4) * H3 + 255) / 256, 256>>>(W3, W3p, H2 / 2, H3);

    gemm_hmma<D_IN, 0, 0, H1><<<dim3(E_TOT / 128, H1 / 128), 256, SMEM_BYTES>>>(
        hfeat, hnodes, hgfeat, ind, W1p, b1, hY1, nullptr);

    gemm_hmma<H1, 1, 0, H2><<<dim3(E_TOT / 128, H2 / 128), 256, SMEM_BYTES>>>(
        hY1, nullptr, nullptr, nullptr, W2p, b2, hY2, nullptr);

    gemm_hmma<H2, 1, 1, H3><<<dim3(E_TOT / 128, H3 / 128), 256, SMEM_BYTES>>>(
        hY2, nullptr, nullptr, nullptr, W3p, b3, nullptr, Hf);

    k_ln<<<E_TOT / 8, 256>>>(Hf, gamma, beta, out);
}

// round 17
// speedup vs baseline: 1.0790x; 1.0790x over previous
#include <cuda_runtime.h>
#include <cuda_fp16.h>
#include <cstdint>
#include <math.h>

#define E_TOT 102400
#define N_TOT 100000
#define NGRAPH 64
#define D_IN   1408
#define H1     512
#define H2     512
#define H3     256

// ---------------- scratch (__device__ globals; no allocs allowed) ----------
__device__ __half   g_hfeat[(size_t)E_TOT * 256];
__device__ __half   g_hnodes[(size_t)N_TOT * 256];
__device__ __half   g_hgfeat[(size_t)NGRAPH * 128];
__device__ uint32_t g_W1p[(size_t)(D_IN / 2) * H1];   // half2(k,k+1) packed, rows k2
__device__ uint32_t g_W2p[(size_t)(H1 / 2) * H2];
__device__ uint32_t g_W3p[(size_t)(H2 / 2) * H3];
__device__ __half   g_hY1[(size_t)E_TOT * H1];
__device__ __half   g_hY2[(size_t)E_TOT * H2];
__device__ float    g_Hf[(size_t)E_TOT * H3];         // sigmoid out (fp32) for LN
__device__ int      g_gcum[NGRAPH + 1];

// ---------------- helpers ---------------------------------------------------
#define CP_ASYNC16(dst, src) \
    asm volatile("cp.async.cg.shared.global [%0], [%1], 16;" :: "r"(dst), "l"(src) : "memory")
#define CP_COMMIT() asm volatile("cp.async.commit_group;" ::: "memory")
#define CP_WAIT(n)  asm volatile("cp.async.wait_group %0;" :: "n"(n) : "memory")

__device__ __forceinline__ uint32_t smem_u32(const void* p) {
    uint32_t a;
    asm("{ .reg .u64 t; cvta.to.shared.u64 t, %1; cvt.u32.u64 %0, t; }"
        : "=r"(a) : "l"(p));
    return a;
}

// m16n8k16 fp16 mma, fp32 accumulate
__device__ __forceinline__ void mma_f16(float* c, const uint32_t* a,
                                        uint32_t b0, uint32_t b1) {
    asm volatile(
        "mma.sync.aligned.m16n8k16.row.col.f32.f16.f16.f32 "
        "{%0,%1,%2,%3}, {%4,%5,%6,%7}, {%8,%9}, {%0,%1,%2,%3};"
        : "+f"(c[0]), "+f"(c[1]), "+f"(c[2]), "+f"(c[3])
        : "r"(a[0]), "r"(a[1]), "r"(a[2]), "r"(a[3]), "r"(b0), "r"(b1));
}

// ---------------- pre-pass kernels ------------------------------------------
__global__ void k_prefix(const int* __restrict__ num) {
    if (threadIdx.x == 0) {
        int s = 0;
        g_gcum[0] = 0;
        for (int i = 0; i < NGRAPH; i++) { s += num[i]; g_gcum[i + 1] = s; }
    }
}

// fp32 -> fp16, vectorized (n4 = count/4)
__global__ void __launch_bounds__(256) k_cvt(
    const float4* __restrict__ src, uint2* __restrict__ dst, int n4)
{
    int i = blockIdx.x * 256 + threadIdx.x;
    if (i < n4) {
        float4 v = src[i];
        __half2 lo = __floats2half2_rn(v.x, v.y);
        __half2 hi = __floats2half2_rn(v.z, v.w);
        uint2 o;
        o.x = *(uint32_t*)&lo;
        o.y = *(uint32_t*)&hi;
        dst[i] = o;
    }
}

// pack one weight entry: Wp[k2][n] = half2(W[2k2][n], W[2k2+1][n])
__device__ __forceinline__ void packW_one(
    const float* __restrict__ W, uint32_t* __restrict__ Wp, int idx, int N)
{
    int k2 = idx / N, n = idx - k2 * N;
    __half2 v = __floats2half2_rn(W[(size_t)(2 * k2) * N + n],
                                  W[(size_t)(2 * k2 + 1) * N + n]);
    Wp[idx] = *(uint32_t*)&v;
}

// single kernel packing all three weights (keeps launch count low so ncu's
// -s 5 -c 1 lands on GEMM1)
__global__ void __launch_bounds__(256) k_packW_all(
    const float* __restrict__ W1, const float* __restrict__ W2,
    const float* __restrict__ W3)
{
    constexpr int n1 = (D_IN / 2) * H1;
    constexpr int n2 = (H1 / 2) * H2;
    constexpr int n3 = (H2 / 2) * H3;
    int i = blockIdx.x * 256 + threadIdx.x;
    if (i < n1)                packW_one(W1, g_W1p, i, H1);
    else if (i < n1 + n2)      packW_one(W2, g_W2p, i - n1, H2);
    else if (i < n1 + n2 + n3) packW_one(W3, g_W3p, i - n1 - n2, H3);
}

// ---------------- fp16 tensor-core GEMM (BK=64 chunks) ----------------------
// BM=128, BN=128, BK=64 (32 k2). 8 warps (4M x 2N), warp tile 32x64.
// A smem: 128 rows x 36 u32 (32 data + pad)  — frag banks (4g+t): conflict-free
// B smem: 32 k2-rows x 136 u32 (128 data+pad) — frag banks (8t+g): conflict-free
// 3 cp.async stages (35,840 B each -> 2 CTAs/SM), one __syncthreads per chunk,
// fragments processed in 2-ks pairs (register footprint = R14).
// MODE 0: A gathered fp16 (hfeat|hnodes[ind]|hgfeat); MODE 1: A = dense fp16.
// EPI 0: relu -> fp16 Yh;  EPI 1: sigmoid -> fp32 Yf.
template<int KDIM, int MODE, int EPI, int HOUT>
__global__ void __launch_bounds__(256, 2) gemm_hmma(
    const __half* __restrict__ Af, const __half* __restrict__ nodes,
    const __half* __restrict__ gfeat, const int* __restrict__ ind,
    const uint32_t* __restrict__ Wp, const float* __restrict__ bias,
    __half* __restrict__ Yh, float* __restrict__ Yf)
{
    constexpr int PAH = 36, PBN = 136;
    constexpr int STAGEU = 128 * PAH + 32 * PBN;     // 8960 u32 / stage
    constexpr int NC = KDIM / 64;

    extern __shared__ uint32_t smU[];

    const int tid  = threadIdx.x;
    const int wid  = tid >> 5;
    const int lane = tid & 31;
    const int warpM = wid & 3;
    const int warpN = wid >> 2;
    const int eBase = blockIdx.x * 128;
    const int nBase = blockIdx.y * 128;

    const int grp = lane >> 2;       // 0..7
    const int tig = lane & 3;        // 0..3

    float acc[2][8][4];
    #pragma unroll
    for (int i = 0; i < 2; i++)
        #pragma unroll
        for (int j = 0; j < 8; j++)
            #pragma unroll
            for (int u = 0; u < 4; u++) acc[i][j][u] = 0.f;

    // ---- chunk loader (64 k = 128B per A row) ------------------------------
    const int arow  = tid >> 1;
    const int apart = tid & 1;       // which 32-half half of the row chunk

    auto load_chunk = [&](int c) {
        uint32_t* As = smU + (c % 3) * STAGEU;
        uint32_t* Bs = As + 128 * PAH;
        const int k0 = c * 64;
        // ---- A  (64-half chunk lies in ONE source segment: 256|256*4|128 all
        //          divisible by 64)
        const __half* asrc;
        if (MODE == 0) {
            const int e = eBase + arow;
            if (k0 < 256) {
                asrc = Af + (size_t)e * 256 + k0;
            } else if (k0 < 1280) {
                const int j   = (k0 - 256) >> 8;
                const int nid = __ldg(ind + e * 4 + j);
                asrc = nodes + (size_t)nid * 256 + ((k0 - 256) & 255);
            } else {
                int lo = 0, hi = NGRAPH;
                while (hi - lo > 1) {
                    int mid = (lo + hi) >> 1;
                    if (g_gcum[mid] <= e) lo = mid; else hi = mid;
                }
                asrc = gfeat + (size_t)lo * 128 + (k0 - 1280);
            }
        } else {
            asrc = Af + (size_t)(eBase + arow) * KDIM + k0;
        }
        asrc += apart * 32;                       // halfs
        uint32_t adst = smem_u32(As + arow * PAH + apart * 16);
        #pragma unroll
        for (int q = 0; q < 4; q++)
            CP_ASYNC16(adst + q * 16, asrc + q * 8);
        // ---- B (Wp rows k2 = c*32 .. +31, 128 u32 wide)
        #pragma unroll
        for (int i = 0; i < 4; i++) {
            const int c16 = tid + 256 * i;        // 0..1023 16B-chunks
            const int row = c16 >> 5;             // 0..31
            const int col = (c16 & 31) * 4;       // u32 col
            const uint32_t* bsrc = Wp + (size_t)(c * 32 + row) * HOUT + nBase + col;
            CP_ASYNC16(smem_u32(Bs + row * PBN + col), bsrc);
        }
        CP_COMMIT();
    };

    // ---- prologue: 2 chunks in flight --------------------------------------
    load_chunk(0);
    if (NC > 1) load_chunk(1);

    uint32_t a[2][2][4];        // [buf][mi][frag]
    uint32_t b[2][8][2];        // [buf][ni][b0/b1]

    for (int c = 0; c < NC; c++) {
        if (c + 1 < NC) CP_WAIT(1); else CP_WAIT(0);
        __syncthreads();
        if (c + 2 < NC) load_chunk(c + 2);

        const uint32_t* As = smU + (c % 3) * STAGEU;
        const uint32_t* Bs = As + 128 * PAH;

        #pragma unroll
        for (int half = 0; half < 2; half++) {
            // load fragments for ks-pair (2*half, 2*half+1)
            #pragma unroll
            for (int ks = 0; ks < 2; ks++) {
                const int k2 = (half * 2 + ks) * 8 + tig;
                #pragma unroll
                for (int mi = 0; mi < 2; mi++) {
                    const int m = warpM * 32 + mi * 16 + grp;
                    a[ks][mi][0] = As[m * PAH + k2];
                    a[ks][mi][1] = As[(m + 8) * PAH + k2];
                    a[ks][mi][2] = As[m * PAH + k2 + 4];
                    a[ks][mi][3] = As[(m + 8) * PAH + k2 + 4];
                }
                #pragma unroll
                for (int ni = 0; ni < 8; ni++) {
                    const int n = warpN * 64 + ni * 8 + grp;
                    b[ks][ni][0] = Bs[k2 * PBN + n];
                    b[ks][ni][1] = Bs[(k2 + 4) * PBN + n];
                }
            }
            #pragma unroll
            for (int ks = 0; ks < 2; ks++)
                #pragma unroll
                for (int ni = 0; ni < 8; ni++) {
                    mma_f16(acc[0][ni], a[ks][0], b[ks][ni][0], b[ks][ni][1]);
                    mma_f16(acc[1][ni], a[ks][1], b[ks][ni][0], b[ks][ni][1]);
                }
        }
    }

    // ---- epilogue ----------------------------------------------------------
    #pragma unroll
    for (int ni = 0; ni < 8; ni++) {
        const int col = nBase + warpN * 64 + ni * 8 + tig * 2;
        const float2 bb = *(const float2*)(bias + col);
        #pragma unroll
        for (int mi = 0; mi < 2; mi++) {
            const int e0 = eBase + warpM * 32 + mi * 16 + grp;
            #pragma unroll
            for (int h = 0; h < 2; h++) {
                float x0 = acc[mi][ni][h * 2 + 0] + bb.x;
                float x1 = acc[mi][ni][h * 2 + 1] + bb.y;
                const size_t off = (size_t)(e0 + h * 8) * HOUT + col;
                if (EPI == 0) {
                    __half2 v = __floats2half2_rn(fmaxf(x0, 0.f), fmaxf(x1, 0.f));
                    *(uint32_t*)(Yh + off) = *(uint32_t*)&v;
                } else {
                    float2 v;
                    v.x = 1.f / (1.f + __expf(-x0));
                    v.y = 1.f / (1.f + __expf(-x1));
                    *(float2*)(Yf + off) = v;
                }
            }
        }
    }
}

// ---------------- LayerNorm over last dim (256) ------------------------------
__global__ void __launch_bounds__(256) k_ln(
    const float* __restrict__ H, const float* __restrict__ gamma,
    const float* __restrict__ beta, float* __restrict__ out)
{
    const int row  = blockIdx.x * 8 + (threadIdx.x >> 5);
    const int lane = threadIdx.x & 31;
    const float* hp = H + (size_t)row * 256 + lane * 8;
    float4 v0 = *(const float4*)(hp);
    float4 v1 = *(const float4*)(hp + 4);
    float s  = v0.x + v0.y + v0.z + v0.w + v1.x + v1.y + v1.z + v1.w;
    float sq = v0.x*v0.x + v0.y*v0.y + v0.z*v0.z + v0.w*v0.w
             + v1.x*v1.x + v1.y*v1.y + v1.z*v1.z + v1.w*v1.w;
    #pragma unroll
    for (int o = 16; o > 0; o >>= 1) {
        s  += __shfl_xor_sync(0xFFFFFFFFu, s,  o);
        sq += __shfl_xor_sync(0xFFFFFFFFu, sq, o);
    }
    const float mu  = s * (1.f / 256.f);
    const float var = sq * (1.f / 256.f) - mu * mu;
    const float rs  = rsqrtf(var + 1e-3f);
    const float4 g0 = *(const float4*)(gamma + lane * 8);
    const float4 g1 = *(const float4*)(gamma + lane * 8 + 4);
    const float4 b0 = *(const float4*)(beta + lane * 8);
    const float4 b1 = *(const float4*)(beta + lane * 8 + 4);
    float4 o0, o1;
    o0.x = g0.x * (v0.x - mu) * rs + b0.x;
    o0.y = g0.y * (v0.y - mu) * rs + b0.y;
    o0.z = g0.z * (v0.z - mu) * rs + b0.z;
    o0.w = g0.w * (v0.w - mu) * rs + b0.w;
    o1.x = g1.x * (v1.x - mu) * rs + b1.x;
    o1.y = g1.y * (v1.y - mu) * rs + b1.y;
    o1.z = g1.z * (v1.z - mu) * rs + b1.z;
    o1.w = g1.w * (v1.w - mu) * rs + b1.w;
    float* op = out + (size_t)row * 256 + lane * 8;
    *(float4*)(op)     = o0;
    *(float4*)(op + 4) = o1;
}

// ---------------------------------------------------------------------------
extern "C" void kernel_launch(void* const* d_in, const int* in_sizes, int n_in,
                              void* d_out, int out_size)
{
    const float* feat  = (const float*)d_in[0];
    const float* nodes = (const float*)d_in[1];
    const float* gfeat = (const float*)d_in[2];
    const int*   ind   = (const int*)  d_in[3];
    const int*   num   = (const int*)  d_in[4];
    const float* W1    = (const float*)d_in[5];
    const float* b1    = (const float*)d_in[6];
    const float* W2    = (const float*)d_in[7];
    const float* b2    = (const float*)d_in[8];
    const float* W3    = (const float*)d_in[9];
    const float* b3    = (const float*)d_in[10];
    const float* gamma = (const float*)d_in[11];
    const float* beta  = (const float*)d_in[12];
    float* out = (float*)d_out;

    const int SMEM_BYTES = 3 * (128 * 36 + 32 * 136) * 4;   // 107520 -> 2 CTAs/SM

    cudaFuncSetAttribute(gemm_hmma<D_IN, 0, 0, H1>,
                         cudaFuncAttributeMaxDynamicSharedMemorySize, SMEM_BYTES);
    cudaFuncSetAttribute(gemm_hmma<H1, 1, 0, H2>,
                         cudaFuncAttributeMaxDynamicSharedMemorySize, SMEM_BYTES);
    cudaFuncSetAttribute(gemm_hmma<H2, 1, 1, H3>,
                         cudaFuncAttributeMaxDynamicSharedMemorySize, SMEM_BYTES);

    __half *hfeat, *hnodes, *hgfeat, *hY1, *hY2;
    uint32_t *W1p, *W2p, *W3p;
    float *Hf;
    cudaGetSymbolAddress((void**)&hfeat,  g_hfeat);
    cudaGetSymbolAddress((void**)&hnodes, g_hnodes);
    cudaGetSymbolAddress((void**)&hgfeat, g_hgfeat);
    cudaGetSymbolAddress((void**)&W1p,    g_W1p);
    cudaGetSymbolAddress((void**)&W2p,    g_W2p);
    cudaGetSymbolAddress((void**)&W3p,    g_W3p);
    cudaGetSymbolAddress((void**)&hY1,    g_hY1);
    cudaGetSymbolAddress((void**)&hY2,    g_hY2);
    cudaGetSymbolAddress((void**)&Hf,     g_Hf);

    // launches 1-5 (so ncu -s 5 -c 1 captures GEMM1 as launch #6)
    k_prefix<<<1, 32>>>(num);
    {
        int n4 = E_TOT * 256 / 4;
        k_cvt<<<(n4 + 255) / 256, 256>>>((const float4*)feat, (uint2*)hfeat, n4);
        n4 = N_TOT * 256 / 4;
        k_cvt<<<(n4 + 255) / 256, 256>>>((const float4*)nodes, (uint2*)hnodes, n4);
        n4 = NGRAPH * 128 / 4;
        k_cvt<<<(n4 + 255) / 256, 256>>>((const float4*)gfeat, (uint2*)hgfeat, n4);
    }
    {
        const int tot = (D_IN / 2) * H1 + (H1 / 2) * H2 + (H2 / 2) * H3;
        k_packW_all<<<(tot + 255) / 256, 256>>>(W1, W2, W3);
    }

    gemm_hmma<D_IN, 0, 0, H1><<<dim3(E_TOT / 128, H1 / 128), 256, SMEM_BYTES>>>(
        hfeat, hnodes, hgfeat, ind, W1p, b1, hY1, nullptr);

    gemm_hmma<H1, 1, 0, H2><<<dim3(E_TOT / 128, H2 / 128), 256, SMEM_BYTES>>>(
        hY1, nullptr, nullptr, nullptr, W2p, b2, hY2, nullptr);

    gemm_hmma<H2, 1, 1, H3><<<dim3(E_TOT / 128, H3 / 128), 256, SMEM_BYTES>>>(
        hY2, nullptr, nullptr, nullptr, W3p, b3, nullptr, Hf);

    k_ln<<<E_TOT / 8, 256>>>(Hf, gamma, beta, out);
}